// round 1
// baseline (speedup 1.0000x reference)
#include <cuda_runtime.h>
#include <cstdint>

// ---------------- problem constants (fixed by the dataset) ----------------
#define NMAX   60000
#define VMAX   50000
#define SEQL   30
#define HD     100      // hidden / feature dim
#define G3     300      // 3 * HD

// ---------------- device scratch (static: no runtime allocation) ----------
__device__ float g_embW[VMAX * G3];     // emb @ W_ih^T + b_ih  (60 MB, L2-resident)
__device__ float g_hn  [NMAX * HD];     // GRU final hidden
__device__ float g_xw  [NMAX * HD];     // x @ W (reused for both convs)
__device__ float g_xc1 [NMAX * HD];     // conv1 output (pre-relu)
__device__ float g_xc2 [NMAX * HD];     // conv2 output (pre-relu)
__device__ float g_x   [NMAX * 2*HD];   // relu(concat(xc1, root1))
__device__ float g_dinv[NMAX];
__device__ int   g_deg [NMAX];

// ---------------- small helpers ----------------
typedef unsigned long long u64;

__device__ __forceinline__ u64 pack2(float lo, float hi) {
    u64 r; asm("mov.b64 %0, {%1, %2};" : "=l"(r) : "f"(lo), "f"(hi)); return r;
}
__device__ __forceinline__ void unpack2(u64 v, float &lo, float &hi) {
    asm("mov.b64 {%0, %1}, %2;" : "=f"(lo), "=f"(hi) : "l"(v));
}
__device__ __forceinline__ u64 fma2(u64 a, u64 b, u64 c) {
    u64 d; asm("fma.rn.f32x2 %0, %1, %2, %3;" : "=l"(d) : "l"(a), "l"(b), "l"(c)); return d;
}
__device__ __forceinline__ float sigmf(float x) {
    return __fdividef(1.f, 1.f + __expf(-x));
}
__device__ __forceinline__ float tanh_f(float x) {
    // tanh(x) = 2*sigmoid(2x) - 1  (exp-based: ~1e-7 abs err, safe for 1e-3 tol)
    return fmaf(2.f, __fdividef(1.f, 1.f + __expf(-2.f * x)), -1.f);
}

// ================= kernel 1: embW[v][g] = sum_k emb[v][k]*W_ih[g][k] + b_ih[g]
__global__ __launch_bounds__(320)
void k_embW(const float* __restrict__ emb, const float* __restrict__ W_ih,
            const float* __restrict__ b_ih)
{
    __shared__ float se[HD];
    int v = blockIdx.x;
    int tid = threadIdx.x;
    if (tid < HD) se[tid] = emb[v * HD + tid];
    __syncthreads();
    if (tid < G3) {
        const float4* w4 = (const float4*)(W_ih + tid * HD);
        float acc = 0.f;
        #pragma unroll
        for (int k4 = 0; k4 < HD/4; k4++) {
            float4 w = w4[k4];
            acc += se[k4*4+0]*w.x + se[k4*4+1]*w.y + se[k4*4+2]*w.z + se[k4*4+3]*w.w;
        }
        g_embW[v * G3 + tid] = acc + b_ih[tid];
    }
}

// ================= degree / normalization =================
__global__ void k_deg_init(int N) {
    int i = blockIdx.x * blockDim.x + threadIdx.x;
    if (i < N) g_deg[i] = 1;             // self-loop
}
__global__ void k_deg_edges(const int* __restrict__ ei, int E) {
    int e = blockIdx.x * blockDim.x + threadIdx.x;
    if (e < E) atomicAdd(&g_deg[ei[E + e]], 1);   // dst = second row
}
__global__ void k_dinv(int N) {
    int i = blockIdx.x * blockDim.x + threadIdx.x;
    if (i < N) g_dinv[i] = rsqrtf((float)g_deg[i]);
}

// ================= kernel 2: fused persistent GRU =================
// 64 nodes per block, 320 threads. Thread (n = tid%64, jc = tid/64 in 0..4)
// computes gh[n][g*100 + jc*20 .. +19] for ALL 3 gates in registers (30 f32x2
// accumulators), then does the gate math locally. h tile lives in SMEM [k][n].
#define GRU_NT  64
#define GRU_TPB 320
#define GRU_SMEM ((30000 + 6400 + 300) * 4 + GRU_NT * SEQL * 4)   // 154480 B

__global__ __launch_bounds__(GRU_TPB, 1)
void k_gru(const float* __restrict__ h0, const int* __restrict__ feat,
           const float* __restrict__ W_hh, const float* __restrict__ b_hh,
           int n_nodes)
{
    extern __shared__ float sm[];
    float* sWt  = sm;             // [100][300]  Wt[k*300+jj] = W_hh[jj][k]
    float* sh   = sm + 30000;     // [100][64]   h[k][n]
    float* sb   = sm + 36400;     // [300]       b_hh
    int*   stok = (int*)(sm + 36700); // [30][64]

    const int tid  = threadIdx.x;
    const int base = blockIdx.x * GRU_NT;
    const int n    = tid & 63;
    const int jc   = tid >> 6;           // 0..4
    const int jbase = jc * 20;

    // --- prologue loads ---
    for (int idx = tid; idx < G3 * HD; idx += GRU_TPB) {
        int jj = idx / HD, k = idx % HD;
        sWt[k * G3 + jj] = W_hh[idx];
    }
    for (int idx = tid; idx < G3; idx += GRU_TPB) sb[idx] = b_hh[idx];
    for (int idx = tid; idx < GRU_NT * SEQL; idx += GRU_TPB) {
        int nn = idx / SEQL, t = idx % SEQL;
        int ng = min(base + nn, n_nodes - 1);
        stok[t * GRU_NT + nn] = feat[ng * SEQL + t];
    }
    for (int idx = tid; idx < GRU_NT * HD; idx += GRU_TPB) {
        int nn = idx / HD, k = idx % HD;
        int ng = min(base + nn, n_nodes - 1);
        sh[k * GRU_NT + nn] = h0[ng * HD + k];
    }
    __syncthreads();

    for (int step = 0; step < SEQL; step++) {
        // ---- GEMM phase: acc[g][j] = sum_k h[n][k] * W_hh[g*100+j][k] ----
        u64 ar[10], az[10], an[10];
        #pragma unroll
        for (int p = 0; p < 10; p++) { ar[p] = 0ull; az[p] = 0ull; an[p] = 0ull; }

        #pragma unroll 2
        for (int k = 0; k < HD; k++) {
            float hk = sh[k * GRU_NT + n];
            u64 hk2 = pack2(hk, hk);
            const float* wr = sWt + k * G3 + jbase;
            #pragma unroll
            for (int p2 = 0; p2 < 5; p2++) {
                ulonglong2 wv = *(const ulonglong2*)(wr + p2 * 4);
                ar[2*p2]   = fma2(wv.x, hk2, ar[2*p2]);
                ar[2*p2+1] = fma2(wv.y, hk2, ar[2*p2+1]);
                ulonglong2 zv = *(const ulonglong2*)(wr + 100 + p2 * 4);
                az[2*p2]   = fma2(zv.x, hk2, az[2*p2]);
                az[2*p2+1] = fma2(zv.y, hk2, az[2*p2+1]);
                ulonglong2 nv = *(const ulonglong2*)(wr + 200 + p2 * 4);
                an[2*p2]   = fma2(nv.x, hk2, an[2*p2]);
                an[2*p2+1] = fma2(nv.y, hk2, an[2*p2+1]);
            }
        }
        __syncthreads();   // everyone done reading sh before it is overwritten

        // ---- gate phase (all three gates are in this thread's registers) ----
        int tok = stok[step * GRU_NT + n];
        const float* ew = g_embW + (long long)tok * G3;
        #pragma unroll
        for (int q = 0; q < 5; q++) {
            int j0 = jbase + q * 4;
            float4 wxr = *(const float4*)(ew + j0);
            float4 wxz = *(const float4*)(ew + 100 + j0);
            float4 wxn = *(const float4*)(ew + 200 + j0);
            float4 brv = *(const float4*)(sb + j0);
            float4 bzv = *(const float4*)(sb + 100 + j0);
            float4 bnv = *(const float4*)(sb + 200 + j0);
            float gr[4], gz[4], gn[4];
            unpack2(ar[2*q], gr[0], gr[1]); unpack2(ar[2*q+1], gr[2], gr[3]);
            unpack2(az[2*q], gz[0], gz[1]); unpack2(az[2*q+1], gz[2], gz[3]);
            unpack2(an[2*q], gn[0], gn[1]); unpack2(an[2*q+1], gn[2], gn[3]);
            float wr_[4] = {wxr.x, wxr.y, wxr.z, wxr.w};
            float wz_[4] = {wxz.x, wxz.y, wxz.z, wxz.w};
            float wn_[4] = {wxn.x, wxn.y, wxn.z, wxn.w};
            float br_[4] = {brv.x, brv.y, brv.z, brv.w};
            float bz_[4] = {bzv.x, bzv.y, bzv.z, bzv.w};
            float bn_[4] = {bnv.x, bnv.y, bnv.z, bnv.w};
            #pragma unroll
            for (int i = 0; i < 4; i++) {
                float ho = sh[(j0 + i) * GRU_NT + n];
                float r  = sigmf(wr_[i] + gr[i] + br_[i]);
                float z  = sigmf(wz_[i] + gz[i] + bz_[i]);
                float nn = tanh_f(wn_[i] + r * (gn[i] + bn_[i]));
                sh[(j0 + i) * GRU_NT + n] = nn + z * (ho - nn);
            }
        }
        __syncthreads();   // h fully updated before next step's reads
    }

    // --- epilogue: write hn ---
    for (int idx = tid; idx < GRU_NT * HD; idx += GRU_TPB) {
        int nn = idx / HD, k = idx % HD;
        int ng = base + nn;
        if (ng < n_nodes) g_hn[ng * HD + k] = sh[k * GRU_NT + nn];
    }
}

// ================= generic small GEMM: out[N,100] = x[N,K] @ W[K,100] ======
template<int K>
__device__ __forceinline__ void gemm_body(const float* __restrict__ x,
                                          const float* __restrict__ W,
                                          float* __restrict__ outp, int N)
{
    extern __shared__ float sg[];
    float* sxT = sg;            // [K][64]
    float* sW  = sg + K * 64;   // [K][100]
    const int tid  = threadIdx.x;
    const int base = blockIdx.x * 64;
    for (int idx = tid; idx < K * 64; idx += 256) {
        int nn = idx / K, k = idx % K;
        int ng = min(base + nn, N - 1);
        sxT[k * 64 + nn] = x[ng * K + k];
    }
    for (int idx = tid; idx < K * 100; idx += 256) sW[idx] = W[idx];
    __syncthreads();

    const int n = tid & 63;
    const int q = tid >> 6;          // 0..3 -> 25 outputs each
    float acc[25];
    #pragma unroll
    for (int j = 0; j < 25; j++) acc[j] = 0.f;
    #pragma unroll 4
    for (int k = 0; k < K; k++) {
        float xk = sxT[k * 64 + n];
        const float* wr = sW + k * 100 + q * 25;
        #pragma unroll
        for (int j = 0; j < 25; j++) acc[j] = fmaf(xk, wr[j], acc[j]);
    }
    int ng = base + n;
    if (ng < N) {
        float* o = outp + ng * 100 + q * 25;
        #pragma unroll
        for (int j = 0; j < 25; j++) o[j] = acc[j];
    }
}

__global__ __launch_bounds__(256) void k_gemm1(const float* __restrict__ W1, int N) {
    gemm_body<100>(g_hn, W1, g_xw, N);
}
__global__ __launch_bounds__(256) void k_gemm2(const float* __restrict__ W2, int N) {
    gemm_body<200>(g_x, W2, g_xw, N);
}

// ================= GCN self-term init + edge aggregation ===================
__device__ __forceinline__ void init_self(const float* __restrict__ b,
                                          float* __restrict__ outp, int N)
{
    int gid = blockIdx.x * blockDim.x + threadIdx.x;
    if (gid >= N * HD) return;
    int n = gid / HD, j = gid - n * HD;
    float di = g_dinv[n];
    outp[gid] = fmaf(g_xw[gid], di * di, b[j]);
}
__global__ void k_init1(const float* __restrict__ b1, int N) { init_self(b1, g_xc1, N); }
__global__ void k_init2(const float* __restrict__ b2, int N) { init_self(b2, g_xc2, N); }

__device__ __forceinline__ void edge_body(float* __restrict__ outp,
                                          const int* __restrict__ ei, int E)
{
    int gid = blockIdx.x * blockDim.x + threadIdx.x;
    if (gid >= E * 25) return;
    int e = gid / 25;
    int c = gid - e * 25;
    int src = ei[e];
    int dst = ei[E + e];
    float coef = g_dinv[src] * g_dinv[dst];
    float4 v = *(const float4*)(g_xw + src * HD + c * 4);
    float* o = outp + dst * HD + c * 4;
    atomicAdd(o + 0, v.x * coef);
    atomicAdd(o + 1, v.y * coef);
    atomicAdd(o + 2, v.z * coef);
    atomicAdd(o + 3, v.w * coef);
}
__global__ void k_edge1(const int* __restrict__ ei, int E) { edge_body(g_xc1, ei, E); }
__global__ void k_edge2(const int* __restrict__ ei, int E) { edge_body(g_xc2, ei, E); }

// ================= concat/relu glue =================
__global__ void k_build_x(const int* __restrict__ indices, int N) {
    int gid = blockIdx.x * blockDim.x + threadIdx.x;
    if (gid >= N * 2 * HD) return;
    int n = gid / (2 * HD), j = gid - n * 2 * HD;
    float v = (j < HD) ? g_xc1[n * HD + j]
                       : g_hn[indices[n] * HD + (j - HD)];
    g_x[gid] = fmaxf(v, 0.f);
}
__global__ void k_final(const int* __restrict__ indices, float* __restrict__ out, int N) {
    int gid = blockIdx.x * blockDim.x + threadIdx.x;
    if (gid >= N * 2 * HD) return;
    int n = gid / (2 * HD), j = gid - n * 2 * HD;
    float v = (j < HD) ? fmaxf(g_xc2[n * HD + j], 0.f)
                       : g_xc1[indices[n] * HD + (j - HD)];   // root2 pre-relu
    out[gid] = v;
}

// ================= launch =================
extern "C" void kernel_launch(void* const* d_in, const int* in_sizes, int n_in,
                              void* d_out, int out_size)
{
    const int*   feat    = (const int*)  d_in[0];
    const int*   ei      = (const int*)  d_in[1];
    const int*   indices = (const int*)  d_in[2];
    const float* h0      = (const float*)d_in[3];
    const float* emb     = (const float*)d_in[4];
    const float* W_ih    = (const float*)d_in[5];
    const float* W_hh    = (const float*)d_in[6];
    const float* b_ih    = (const float*)d_in[7];
    const float* b_hh    = (const float*)d_in[8];
    const float* W1      = (const float*)d_in[9];
    const float* b1      = (const float*)d_in[10];
    const float* W2      = (const float*)d_in[11];
    const float* b2      = (const float*)d_in[12];
    float* out = (float*)d_out;

    const int N = in_sizes[0] / SEQL;     // 60000
    const int E = in_sizes[1] / 2;        // 120000
    const int V = in_sizes[4] / HD;       // 50000

    cudaFuncSetAttribute(k_gru,   cudaFuncAttributeMaxDynamicSharedMemorySize, GRU_SMEM);
    cudaFuncSetAttribute(k_gemm1, cudaFuncAttributeMaxDynamicSharedMemorySize, (100*64 + 100*100) * 4);
    cudaFuncSetAttribute(k_gemm2, cudaFuncAttributeMaxDynamicSharedMemorySize, (200*64 + 200*100) * 4);

    // 1) input-projection table + degree normalization
    k_embW<<<V, 320>>>(emb, W_ih, b_ih);
    k_deg_init <<<(N + 255) / 256, 256>>>(N);
    k_deg_edges<<<(E + 255) / 256, 256>>>(ei, E);
    k_dinv     <<<(N + 255) / 256, 256>>>(N);

    // 2) fused persistent GRU
    k_gru<<<(N + GRU_NT - 1) / GRU_NT, GRU_TPB, GRU_SMEM>>>(h0, feat, W_hh, b_hh, N);

    // 3) GCN conv 1
    k_gemm1<<<(N + 63) / 64, 256, (100*64 + 100*100) * 4>>>(W1, N);
    k_init1<<<(N * HD + 255) / 256, 256>>>(b1, N);
    k_edge1<<<(E * 25 + 255) / 256, 256>>>(ei, E);

    // 4) concat + relu
    k_build_x<<<(N * 2 * HD + 255) / 256, 256>>>(indices, N);

    // 5) GCN conv 2
    k_gemm2<<<(N + 63) / 64, 256, (200*64 + 200*100) * 4>>>(W2, N);
    k_init2<<<(N * HD + 255) / 256, 256>>>(b2, N);
    k_edge2<<<(E * 25 + 255) / 256, 256>>>(ei, E);

    // 6) final concat
    k_final<<<(N * 2 * HD + 255) / 256, 256>>>(indices, out, N);
}